// round 3
// baseline (speedup 1.0000x reference)
#include <cuda_runtime.h>
#include <cuda.h>
#include <cuda_fp16.h>
#include <cstdint>

#define B_DIM  4096
#define K_DIM  1024
#define NSOMA  16384
#define NNEUR  1024

#define MT     128
#define NT     256
#define KC     64
#define NKC    (K_DIM / KC)

#define STAGE_A (MT * KC * 2)
#define STAGE_B (NT * KC * 2)
#define STAGE_BYTES (STAGE_A + STAGE_B)

#define SM_CTRL     (2 * STAGE_BYTES)
#define SM_TMEMPTR  (SM_CTRL + 0)
#define SM_FULL(st) (SM_CTRL + 16 + 8*(st))
#define SM_EMPTY(st)(SM_CTRL + 32 + 8*(st))
#define SM_FINAL    (SM_CTRL + 48)
#define SM_BD       (SM_CTRL + 64)
#define SM_WS       (SM_BD + NT*4)
#define SM_BS       (SM_WS + NT*4)
#define SMEM_BYTES  (SM_BS + 64 + 1024)

// idesc kind::f16: D=F32(bit4), atype=btype=F16(0), N=256, M=128
#define MMA_IDESC ((1u << 4) | ((NT / 8) << 17) | ((MT / 16) << 24))

// tcgen05 available only when the arch-specific ('a') target is compiled
#if defined(__CUDA_ARCH_FEAT_SM103_ALL) || defined(__CUDA_ARCH_FEAT_SM100_ALL) || defined(__CUDA_ARCH_FEAT_SM101_ALL)
#define HAVE_TCGEN05 1
#else
#define HAVE_TCGEN05 0
#endif

__device__ __align__(1024) __half g_X16[(size_t)B_DIM * K_DIM];
__device__ __align__(1024) __half g_W16[(size_t)NSOMA * K_DIM];

static __device__ __forceinline__ uint32_t smem_u32(const void* p) {
    uint32_t a;
    asm("{ .reg .u64 t; cvta.to.shared.u64 t, %1; cvt.u32.u64 %0, t; }" : "=r"(a) : "l"(p));
    return a;
}

#define MBAR_INIT(a, c) \
    asm volatile("mbarrier.init.shared.b64 [%0], %1;" :: "r"((uint32_t)(a)), "r"((uint32_t)(c)) : "memory")
#define MBAR_EXPECT_TX(a, b) \
    asm volatile("mbarrier.arrive.expect_tx.shared.b64 _, [%0], %1;" :: "r"((uint32_t)(a)), "r"((uint32_t)(b)) : "memory")
#define MBAR_WAIT(a, p) do {                                                     \
    uint32_t _m = (uint32_t)(a), _p = (uint32_t)(p), _d;                         \
    asm volatile("{\n\t.reg .pred q;\n\t"                                        \
        "mbarrier.try_wait.parity.acquire.cta.shared::cta.b64 q, [%1], %2;\n\t"  \
        "selp.b32 %0, 1, 0, q;\n\t}" : "=r"(_d) : "r"(_m), "r"(_p) : "memory");  \
    if (!_d) {                                                                   \
        asm volatile("{\n\t.reg .pred Q;\n\t"                                    \
            "WL_%=:\n\t"                                                         \
            "mbarrier.try_wait.parity.acquire.cta.shared::cta.b64 Q, [%0], %1, 0x989680;\n\t" \
            "@Q bra.uni WD_%=;\n\tbra.uni WL_%=;\n\tWD_%=:\n\t}"                 \
            :: "r"(_m), "r"(_p) : "memory");                                     \
    }                                                                            \
} while (0)

#define TMA_2D(dst, tm, cx, cy, mbar) \
    asm volatile("cp.async.bulk.tensor.2d.shared::cta.global.tile.mbarrier::complete_tx::bytes " \
                 "[%0], [%1, {%2, %3}], [%4];" \
                 :: "r"((uint32_t)(dst)), "l"(tm), "r"((int32_t)(cx)), "r"((int32_t)(cy)), \
                    "r"((uint32_t)(mbar)) : "memory")

#if HAVE_TCGEN05
#define TC_COMMIT(mbar) \
    asm volatile("tcgen05.commit.cta_group::1.mbarrier::arrive::one.shared::cluster.b64 [%0];" \
                 :: "r"((uint32_t)(mbar)) : "memory")

// SW128 K-major smem desc: layout=2, version=1, SBO=64, LBO=1
static __device__ __forceinline__ uint64_t make_desc(uint32_t addr) {
    const uint64_t base = (uint64_t(2) << 61) | (uint64_t(1) << 46) |
                          (uint64_t(64) << 32) | (uint64_t(1) << 16);
    return base | ((uint64_t)(addr >> 4) & 0x3FFF);
}

static __device__ __forceinline__ void mma_f16_ss(
    uint32_t d, uint64_t ad, uint64_t bd, uint32_t idesc, bool acc)
{
    uint32_t en = acc ? 1u : 0u;
    asm volatile(
        "{\n\t.reg .pred p;\n\t"
        "setp.ne.u32 p, %5, 0;\n\t"
        "tcgen05.mma.cta_group::1.kind::f16 [%0], %1, %2, %3, {%4, %4, %4, %4}, p;\n\t}"
        :: "r"(d), "l"(ad), "l"(bd), "r"(idesc), "r"(0u), "r"(en) : "memory");
}

#define LDTM32(r, a) \
    asm volatile("tcgen05.ld.sync.aligned.32x32b.x32.b32 " \
        "{%0,%1,%2,%3,%4,%5,%6,%7,%8,%9,%10,%11,%12,%13,%14,%15," \
        "%16,%17,%18,%19,%20,%21,%22,%23,%24,%25,%26,%27,%28,%29,%30,%31}, [%32];" \
        : "=r"((r)[0]),"=r"((r)[1]),"=r"((r)[2]),"=r"((r)[3]),"=r"((r)[4]),"=r"((r)[5]), \
          "=r"((r)[6]),"=r"((r)[7]),"=r"((r)[8]),"=r"((r)[9]),"=r"((r)[10]),"=r"((r)[11]), \
          "=r"((r)[12]),"=r"((r)[13]),"=r"((r)[14]),"=r"((r)[15]),"=r"((r)[16]),"=r"((r)[17]), \
          "=r"((r)[18]),"=r"((r)[19]),"=r"((r)[20]),"=r"((r)[21]),"=r"((r)[22]),"=r"((r)[23]), \
          "=r"((r)[24]),"=r"((r)[25]),"=r"((r)[26]),"=r"((r)[27]),"=r"((r)[28]),"=r"((r)[29]), \
          "=r"((r)[30]),"=r"((r)[31]) : "r"(a))
#endif  // HAVE_TCGEN05

// ---------- prep: fp32 -> fp16 (mask folded into W) ----------
__global__ void cvt_x_kernel(const float4* __restrict__ x, __half2* __restrict__ o, int n4)
{
    int i = blockIdx.x * blockDim.x + threadIdx.x;
    if (i < n4) {
        float4 v = x[i];
        o[2*i]   = __floats2half2_rn(v.x, v.y);
        o[2*i+1] = __floats2half2_rn(v.z, v.w);
    }
}

__global__ void cvt_w_kernel(const float4* __restrict__ w, const float4* __restrict__ m,
                             __half2* __restrict__ o, int n4)
{
    int i = blockIdx.x * blockDim.x + threadIdx.x;
    if (i < n4) {
        float4 v = w[i]; float4 k = m[i];
        o[2*i]   = __floats2half2_rn(v.x * k.x, v.y * k.y);
        o[2*i+1] = __floats2half2_rn(v.z * k.z, v.w * k.w);
    }
}

// ---------- fused GEMM + bias + leaky + block-diag layer 2 ----------
__global__ void __launch_bounds__(128, 2)
fused_gemm(const __grid_constant__ CUtensorMap tmA,
           const __grid_constant__ CUtensorMap tmB,
           const float* __restrict__ bd, const float* __restrict__ Ws,
           const float* __restrict__ bs, float* __restrict__ out)
{
    extern __shared__ uint8_t smem_raw[];
    const uint32_t sraw = smem_u32(smem_raw);
    const uint32_t sb   = (sraw + 1023u) & ~1023u;
    char* sp = (char*)smem_raw + (sb - sraw);

    const int tid = threadIdx.x;
    const int n_tile = blockIdx.x;
    const int m_tile = blockIdx.y;

    float* bd_s = (float*)(sp + SM_BD);
    float* ws_s = (float*)(sp + SM_WS);
    float* bs_s = (float*)(sp + SM_BS);
    {
        const int nb = n_tile * NT;
        bd_s[tid]       = bd[nb + tid];
        bd_s[tid + 128] = bd[nb + tid + 128];
        #pragma unroll
        for (int t = tid; t < NT; t += 128) {
            int g = t >> 4, d = t & 15;
            int n = n_tile * 16 + g;
            ws_s[t] = Ws[(size_t)n * NSOMA + n * 16 + d];
        }
        if (tid < 16) bs_s[tid] = bs[n_tile * 16 + tid];
    }

#if HAVE_TCGEN05
    const int wid = tid >> 5;
    if (wid == 0) {
        asm volatile("tcgen05.alloc.cta_group::1.sync.aligned.shared::cta.b32 [%0], %1;"
                     :: "r"(sb + SM_TMEMPTR), "r"(256u) : "memory");
        asm volatile("tcgen05.relinquish_alloc_permit.cta_group::1.sync.aligned;");
    }
    if (tid == 0) {
        MBAR_INIT(sb + SM_FULL(0), 1);  MBAR_INIT(sb + SM_FULL(1), 1);
        MBAR_INIT(sb + SM_EMPTY(0), 1); MBAR_INIT(sb + SM_EMPTY(1), 1);
        MBAR_INIT(sb + SM_FINAL, 1);
    }
    __syncthreads();

    uint32_t tmem;
    asm volatile("ld.shared.b32 %0, [%1];" : "=r"(tmem) : "r"(sb + SM_TMEMPTR));

    if (tid == 0) {
        #pragma unroll
        for (int p = 0; p < 2; ++p) {
            MBAR_EXPECT_TX(sb + SM_FULL(p), STAGE_BYTES);
            TMA_2D(sb + p*STAGE_BYTES,           &tmA, p*KC, m_tile*MT, sb + SM_FULL(p));
            TMA_2D(sb + p*STAGE_BYTES + STAGE_A, &tmB, p*KC, n_tile*NT, sb + SM_FULL(p));
        }
        for (int kc = 0; kc < NKC; ++kc) {
            const int st = kc & 1;
            const int ph = (kc >> 1) & 1;
            MBAR_WAIT(sb + SM_FULL(st), ph);
            const uint64_t ad = make_desc(sb + st*STAGE_BYTES);
            const uint64_t bdd = make_desc(sb + st*STAGE_BYTES + STAGE_A);
            #pragma unroll
            for (int k4 = 0; k4 < 4; ++k4)
                mma_f16_ss(tmem, ad + 2*k4, bdd + 2*k4, MMA_IDESC, (kc | k4) != 0);
            TC_COMMIT(sb + SM_EMPTY(st));
            const int nxt = kc + 2;
            if (nxt < NKC) {
                MBAR_WAIT(sb + SM_EMPTY(st), ph);
                MBAR_EXPECT_TX(sb + SM_FULL(st), STAGE_BYTES);
                TMA_2D(sb + st*STAGE_BYTES,           &tmA, nxt*KC, m_tile*MT, sb + SM_FULL(st));
                TMA_2D(sb + st*STAGE_BYTES + STAGE_A, &tmB, nxt*KC, n_tile*NT, sb + SM_FULL(st));
            }
        }
        TC_COMMIT(sb + SM_FINAL);
    }

    MBAR_WAIT(sb + SM_FINAL, 0);
    asm volatile("tcgen05.fence::after_thread_sync;" ::: "memory");

    float acc[16];
    #pragma unroll
    for (int i = 0; i < 16; ++i) acc[i] = 0.f;
    #pragma unroll
    for (int cb = 0; cb < 8; ++cb) {
        uint32_t r[32];
        LDTM32(r, tmem + cb*32);
        asm volatile("tcgen05.wait::ld.sync.aligned;" ::: "memory");
        #pragma unroll
        for (int j = 0; j < 32; ++j) {
            int c = cb*32 + j;
            float v = __uint_as_float(r[j]) + bd_s[c];
            v = v >= 0.f ? v : 0.1f * v;
            acc[c >> 4] += v * ws_s[c];
        }
    }
    {
        int row = m_tile*MT + wid*32 + (tid & 31);
        float* op = out + (size_t)row * NNEUR + n_tile * 16;
        #pragma unroll
        for (int g = 0; g < 16; ++g) {
            float v = acc[g] + bs_s[g];
            op[g] = v >= 0.f ? v : 0.1f * v;
        }
    }

    __syncthreads();
    if (wid == 0) {
        asm volatile("tcgen05.dealloc.cta_group::1.sync.aligned.b32 %0, %1;" :: "r"(tmem), "r"(256u));
    }
#else
    // ---------- SIMT fallback (no tcgen05 on this compile target) ----------
    // 4 passes of 32 batch rows; X transposed in smem as half2[k/2][32 rows];
    // each warp owns 64 somas (stride-4), all lanes share the W row (broadcast LDG).
    __half2* Xs2   = (__half2*)sp;                       // [512][32] = 64 KB
    float*   acc_s = (float*)(sp + 66560);               // [32 m][16 neurons]
    const int lane = tid & 31;
    const int cg   = tid >> 5;                           // warp id 0..3
    const __half* Wg = &g_W16[(size_t)(n_tile * NT) * K_DIM];
    __syncthreads();

    for (int pass = 0; pass < 4; ++pass) {
        for (int i = tid; i < 32 * 16; i += 128) acc_s[i] = 0.f;
        __syncthreads();
        {   // load 32 rows of X, transposed into Xs2
            int r  = tid >> 2;
            int kk0 = (tid & 3) * 128;
            const __half2* src = (const __half2*)&g_X16[(size_t)(m_tile*MT + pass*32 + r) * K_DIM];
            for (int kk = 0; kk < 128; ++kk)
                Xs2[(kk0 + kk) * 32 + r] = src[kk0 + kk];
        }
        __syncthreads();

        for (int j = 0; j < 64; ++j) {
            const int cl = cg + 4 * j;                   // soma 0..255 (uniform per warp)
            const int4* wp = (const int4*)&Wg[(size_t)cl * K_DIM];
            float hsum = 0.f;
            for (int kb = 0; kb < K_DIM / 8; kb += 8) {  // 8 int4 = 64 halves per block
                #pragma unroll
                for (int q = 0; q < 8; ++q) {
                    int4 w4 = wp[kb + q];
                    const __half2* w2 = (const __half2*)&w4;
                    __half2 hacc = __float2half2_rn(0.f);
                    #pragma unroll
                    for (int t = 0; t < 4; ++t) {
                        __half2 x2 = Xs2[((kb + q) * 4 + t) * 32 + lane];
                        hacc = __hfma2(w2[t], x2, hacc);
                    }
                    float2 f = __half22float2(hacc);
                    hsum += f.x + f.y;
                }
            }
            float h = hsum + bd_s[cl];
            h = h >= 0.f ? h : 0.1f * h;
            atomicAdd(&acc_s[lane * 16 + (cl >> 4)], h * ws_s[cl]);
        }
        __syncthreads();
        for (int i = tid; i < 32 * 16; i += 128) {
            int m = i >> 4, n = i & 15;
            float v = acc_s[i] + bs_s[n];
            v = v >= 0.f ? v : 0.1f * v;
            out[(size_t)(m_tile*MT + pass*32 + m) * NNEUR + n_tile * 16 + n] = v;
        }
        __syncthreads();
    }
#endif
}

// ---------- host ----------
typedef CUresult (*EncodeFn)(CUtensorMap*, CUtensorMapDataType, cuuint32_t, void*,
                             const cuuint64_t*, const cuuint64_t*, const cuuint32_t*,
                             const cuuint32_t*, CUtensorMapInterleave, CUtensorMapSwizzle,
                             CUtensorMapL2promotion, CUtensorMapFloatOOBfill);

static void make_map(EncodeFn enc, CUtensorMap* map, void* ptr,
                     uint64_t rows, uint32_t box_rows)
{
    cuuint64_t dims[2]    = {K_DIM, rows};
    cuuint64_t strides[1] = {K_DIM * 2};
    cuuint32_t box[2]     = {KC, box_rows};
    cuuint32_t es[2]      = {1, 1};
    enc(map, CU_TENSOR_MAP_DATA_TYPE_FLOAT16, 2, ptr, dims, strides, box, es,
        CU_TENSOR_MAP_INTERLEAVE_NONE, CU_TENSOR_MAP_SWIZZLE_128B,
        CU_TENSOR_MAP_L2_PROMOTION_L2_128B, CU_TENSOR_MAP_FLOAT_OOB_FILL_NONE);
}

extern "C" void kernel_launch(void* const* d_in, const int* in_sizes, int n_in,
                              void* d_out, int out_size)
{
    const float* x    = (const float*)d_in[0];
    const float* Wd   = (const float*)d_in[1];
    const float* bd   = (const float*)d_in[2];
    const float* Ws   = (const float*)d_in[3];
    const float* bs   = (const float*)d_in[4];
    const float* dmask= (const float*)d_in[5];
    float* out = (float*)d_out;

    void* px; void* pw;
    cudaGetSymbolAddress(&px, g_X16);
    cudaGetSymbolAddress(&pw, g_W16);

    cudaDriverEntryPointQueryResult qr;
    void* fn = nullptr;
    cudaGetDriverEntryPointByVersion("cuTensorMapEncodeTiled", &fn, 12000,
                                     cudaEnableDefault, &qr);
    EncodeFn enc = (EncodeFn)fn;

    CUtensorMap tmA, tmB;
    make_map(enc, &tmA, px, B_DIM, MT);
    make_map(enc, &tmB, pw, NSOMA, NT);

    cudaFuncSetAttribute(fused_gemm, cudaFuncAttributeMaxDynamicSharedMemorySize, SMEM_BYTES);

    int n4x = B_DIM * K_DIM / 4;
    int n4w = NSOMA * K_DIM / 4;
    cvt_x_kernel<<<(n4x + 255) / 256, 256>>>((const float4*)x, (__half2*)px, n4x);
    cvt_w_kernel<<<(n4w + 255) / 256, 256>>>((const float4*)Wd, (const float4*)dmask,
                                             (__half2*)pw, n4w);
    dim3 grid(NSOMA / NT, B_DIM / MT);
    fused_gemm<<<grid, 128, SMEM_BYTES>>>(tmA, tmB, bd, Ws, bs, out);
}